// round 2
// baseline (speedup 1.0000x reference)
#include <cuda_runtime.h>
#include <math.h>

// Problem constants
#define BB    8
#define CC    512
#define NN    1024        // H*W = 32*32
#define HEADS 8
#define DK    64
#define QKVC  1536        // HEADS * DK * 3
#define SCALE 0.125f      // DK^-0.5
#define TS    66          // transposed-tile stride (even -> 8B-aligned float2)

// Scratch (device globals; no allocation allowed)
__device__ float g_qkv[BB * NN * QKVC];   // [b*N+n][1536], per head: q(64) k(64) v(64)
__device__ float g_att[BB * NN * CC];     // [b*N+n][h*64+d]

// ---------------------------------------------------------------------------
// Kernel 1: QKV GEMM.  C[m=8192][col=1536] = A[m][k=512] * Wq[k][col] + bq
// A[m][k] = x[b, k, n]  (x is [B, C, N] row-major; m = b*1024 + n)
// 128x128 tile, BK=8, 256 threads, 8x8 microtile.
// ---------------------------------------------------------------------------
__global__ __launch_bounds__(256) void k_qkv(const float* __restrict__ x,
                                             const float* __restrict__ Wq,
                                             const float* __restrict__ bq)
{
    __shared__ float As[8 * 128];   // As[k][m]
    __shared__ float Bs[8 * 128];   // Bs[k][col]

    const int tid = threadIdx.x;
    const int tx  = tid & 15;
    const int ty  = tid >> 4;
    const int lm  = tid & 127;
    const int kb  = (tid >> 7) << 2;      // 0 or 4
    const int bx  = blockIdx.x;           // col tile: 0..11
    const int by  = blockIdx.y;           // m tile:   0..63

    const int b = by >> 3;
    const int n = ((by & 7) << 7) + lm;

    const float* pA = x  + (size_t)b * CC * NN + n;   // + k*NN
    const float* pB = Wq + (size_t)bx * 128 + lm;     // + k*QKVC

    float acc[8][8];
#pragma unroll
    for (int i = 0; i < 8; i++)
#pragma unroll
        for (int j = 0; j < 8; j++) acc[i][j] = 0.f;

    for (int k0 = 0; k0 < CC; k0 += 8) {
#pragma unroll
        for (int i = 0; i < 4; i++) {
            As[(kb + i) * 128 + lm] = pA[(size_t)(k0 + kb + i) * NN];
            Bs[(kb + i) * 128 + lm] = pB[(size_t)(k0 + kb + i) * QKVC];
        }
        __syncthreads();
#pragma unroll
        for (int kk = 0; kk < 8; kk++) {
            float a[8], bv[8];
            *(float4*)&a[0]  = *(float4*)&As[kk * 128 + ty * 4];
            *(float4*)&a[4]  = *(float4*)&As[kk * 128 + 64 + ty * 4];
            *(float4*)&bv[0] = *(float4*)&Bs[kk * 128 + tx * 4];
            *(float4*)&bv[4] = *(float4*)&Bs[kk * 128 + 64 + tx * 4];
#pragma unroll
            for (int i = 0; i < 8; i++)
#pragma unroll
                for (int j = 0; j < 8; j++)
                    acc[i][j] += a[i] * bv[j];
        }
        __syncthreads();
    }

    const int m0 = by * 128;
    const int c0 = bx * 128;
    float bias[8];
    *(float4*)&bias[0] = *(const float4*)&bq[c0 + tx * 4];
    *(float4*)&bias[4] = *(const float4*)&bq[c0 + 64 + tx * 4];

#pragma unroll
    for (int i = 0; i < 8; i++) {
        int m = m0 + ((i < 4) ? (ty * 4 + i) : (64 + ty * 4 + (i - 4)));
        float4 v0, v1;
        v0.x = acc[i][0] + bias[0]; v0.y = acc[i][1] + bias[1];
        v0.z = acc[i][2] + bias[2]; v0.w = acc[i][3] + bias[3];
        v1.x = acc[i][4] + bias[4]; v1.y = acc[i][5] + bias[5];
        v1.z = acc[i][6] + bias[6]; v1.w = acc[i][7] + bias[7];
        *(float4*)&g_qkv[(size_t)m * QKVC + c0 + tx * 4]      = v0;
        *(float4*)&g_qkv[(size_t)m * QKVC + c0 + 64 + tx * 4] = v1;
    }
}

// ---------------------------------------------------------------------------
// Kernel 2: flash attention per (b, h, qtile=64 rows).
// 256 threads as 16(ty=row grp) x 16(tx=col grp), 4x4 microtiles.
// Smem: Qs/Ks/Ps transposed [64][TS=66] (even stride -> aligned float2 loads),
//       Vs natural [64][64] (float4).
// SCALE folded into Q at load.
// ---------------------------------------------------------------------------
__global__ __launch_bounds__(256, 2) void k_attn()
{
    extern __shared__ float sm[];
    float* Qs = sm;               // Qs[d][row]  stride TS
    float* Ks = Qs + 64 * TS;     // Ks[d][key]  stride TS
    float* Ps = Ks + 64 * TS;     // Ps[key][row] stride TS
    float* Vs = Ps + 64 * TS;     // Vs[key][d]  stride 64

    const int tid = threadIdx.x;
    const int tx  = tid & 15;
    const int ty  = tid >> 4;
    const int qt  = blockIdx.x;   // 0..15
    const int h   = blockIdx.y;   // 0..7
    const int b   = blockIdx.z;   // 0..7

    const size_t head_base = (size_t)b * NN * QKVC + (size_t)h * (3 * DK);

    // Load Q tile transposed, scaled
#pragma unroll
    for (int e = 0; e < 4; e++) {
        int idx = tid + e * 256;
        int row = idx >> 4;
        int d4  = (idx & 15) * 4;
        float4 v = *(const float4*)&g_qkv[head_base + (size_t)(qt * 64 + row) * QKVC + d4];
        Qs[(d4 + 0) * TS + row] = v.x * SCALE;
        Qs[(d4 + 1) * TS + row] = v.y * SCALE;
        Qs[(d4 + 2) * TS + row] = v.z * SCALE;
        Qs[(d4 + 3) * TS + row] = v.w * SCALE;
    }

    float o[4][4];
    float mi[4], li[4];
#pragma unroll
    for (int i = 0; i < 4; i++) {
        mi[i] = -1e30f; li[i] = 0.f;
#pragma unroll
        for (int j = 0; j < 4; j++) o[i][j] = 0.f;
    }

    for (int kt = 0; kt < 16; kt++) {
        __syncthreads();   // prev O-GEMM reads of Ks/Vs/Ps done; Qs visible (iter 0)
#pragma unroll
        for (int e = 0; e < 4; e++) {
            int idx = tid + e * 256;
            int row = idx >> 4;
            int d4  = (idx & 15) * 4;
            size_t g = head_base + (size_t)(kt * 64 + row) * QKVC;
            float4 kv = *(const float4*)&g_qkv[g + 64 + d4];
            Ks[(d4 + 0) * TS + row] = kv.x;
            Ks[(d4 + 1) * TS + row] = kv.y;
            Ks[(d4 + 2) * TS + row] = kv.z;
            Ks[(d4 + 3) * TS + row] = kv.w;
            float4 vv = *(const float4*)&g_qkv[g + 128 + d4];
            *(float4*)&Vs[row * 64 + d4] = vv;
        }
        __syncthreads();

        // S = (Q*scale) @ K^T  (4x4 per thread)
        float s[4][4];
#pragma unroll
        for (int i = 0; i < 4; i++)
#pragma unroll
            for (int j = 0; j < 4; j++) s[i][j] = 0.f;

#pragma unroll
        for (int kk = 0; kk < 64; kk++) {
            float2 q01 = *(float2*)&Qs[kk * TS + ty * 4];
            float2 q23 = *(float2*)&Qs[kk * TS + ty * 4 + 2];
            float2 k01 = *(float2*)&Ks[kk * TS + tx * 4];
            float2 k23 = *(float2*)&Ks[kk * TS + tx * 4 + 2];
            float qv[4] = {q01.x, q01.y, q23.x, q23.y};
            float kv[4] = {k01.x, k01.y, k23.x, k23.y};
#pragma unroll
            for (int i = 0; i < 4; i++)
#pragma unroll
                for (int j = 0; j < 4; j++)
                    s[i][j] += qv[i] * kv[j];
        }

        // online softmax per row (16 tx-threads share a row -> shfl reduce)
#pragma unroll
        for (int i = 0; i < 4; i++) {
            float rm = fmaxf(fmaxf(s[i][0], s[i][1]), fmaxf(s[i][2], s[i][3]));
#pragma unroll
            for (int off = 8; off; off >>= 1)
                rm = fmaxf(rm, __shfl_xor_sync(0xffffffffu, rm, off));
            float mnew  = fmaxf(mi[i], rm);
            float alpha = __expf(mi[i] - mnew);
            mi[i] = mnew;
            float rs = 0.f;
#pragma unroll
            for (int j = 0; j < 4; j++) {
                float p = __expf(s[i][j] - mnew);
                s[i][j] = p;
                rs += p;
            }
#pragma unroll
            for (int off = 8; off; off >>= 1)
                rs += __shfl_xor_sync(0xffffffffu, rs, off);
            li[i] = li[i] * alpha + rs;
#pragma unroll
            for (int j = 0; j < 4; j++) o[i][j] *= alpha;
        }

        // store P transposed: Ps[key][row]
#pragma unroll
        for (int i = 0; i < 4; i++)
#pragma unroll
            for (int j = 0; j < 4; j++)
                Ps[(tx * 4 + j) * TS + ty * 4 + i] = s[i][j];
        __syncthreads();

        // O += P @ V
#pragma unroll
        for (int kk = 0; kk < 64; kk++) {
            float2 p01 = *(float2*)&Ps[kk * TS + ty * 4];
            float2 p23 = *(float2*)&Ps[kk * TS + ty * 4 + 2];
            float4 vv  = *(float4*)&Vs[kk * 64 + tx * 4];
            float pv[4] = {p01.x, p01.y, p23.x, p23.y};
            float vr[4] = {vv.x, vv.y, vv.z, vv.w};
#pragma unroll
            for (int i = 0; i < 4; i++)
#pragma unroll
                for (int j = 0; j < 4; j++)
                    o[i][j] += pv[i] * vr[j];
        }
    }

    // normalize + write [bn][h*64+d]
#pragma unroll
    for (int i = 0; i < 4; i++) {
        float inv = 1.f / li[i];
        float4 v;
        v.x = o[i][0] * inv; v.y = o[i][1] * inv;
        v.z = o[i][2] * inv; v.w = o[i][3] * inv;
        int row = qt * 64 + ty * 4 + i;
        *(float4*)&g_att[((size_t)(b * NN + row)) * CC + h * DK + tx * 4] = v;
    }
}

// ---------------------------------------------------------------------------
// Kernel 3: out = att @ W_out + b_out + residual, written as [b][c][n].
// GEMM computed transposed: rows = c (512), cols = bn (8192), K = 512.
// As[k][c] = Wo[e][c] (direct), Bs[k][n] = att[bn][e] (transpose-load).
// ---------------------------------------------------------------------------
__global__ __launch_bounds__(256) void k_proj(const float* __restrict__ Wo,
                                              const float* __restrict__ bo,
                                              const float* __restrict__ x,
                                              float* __restrict__ out)
{
    __shared__ float As[8 * 128];   // As[e][c]
    __shared__ float Bs[8 * 128];   // Bs[e][n]

    const int tid = threadIdx.x;
    const int tx  = tid & 15;
    const int ty  = tid >> 4;
    const int lm  = tid & 127;
    const int kb  = (tid >> 7) << 2;
    const int bx  = blockIdx.x;     // bn tile: 0..63
    const int by  = blockIdx.y;     // c tile:  0..3

    const int nn = tid >> 1;            // 0..127 (B-tile load)
    const int e4 = (tid & 1) * 4;       // 0 or 4
    const int b  = bx >> 3;
    const int bn0 = bx * 128;

    const float* pA = Wo + by * 128 + lm;                        // + e*CC
    const float* pB = g_att + (size_t)(bn0 + nn) * CC + e4;      // + k0

    float acc[8][8];
#pragma unroll
    for (int i = 0; i < 8; i++)
#pragma unroll
        for (int j = 0; j < 8; j++) acc[i][j] = 0.f;

    for (int k0 = 0; k0 < CC; k0 += 8) {
#pragma unroll
        for (int i = 0; i < 4; i++)
            As[(kb + i) * 128 + lm] = pA[(size_t)(k0 + kb + i) * CC];
        float4 bv = *(const float4*)&pB[k0];
        Bs[(e4 + 0) * 128 + nn] = bv.x;
        Bs[(e4 + 1) * 128 + nn] = bv.y;
        Bs[(e4 + 2) * 128 + nn] = bv.z;
        Bs[(e4 + 3) * 128 + nn] = bv.w;
        __syncthreads();
#pragma unroll
        for (int kk = 0; kk < 8; kk++) {
            float a[8], bb[8];
            *(float4*)&a[0]  = *(float4*)&As[kk * 128 + ty * 4];
            *(float4*)&a[4]  = *(float4*)&As[kk * 128 + 64 + ty * 4];
            *(float4*)&bb[0] = *(float4*)&Bs[kk * 128 + tx * 4];
            *(float4*)&bb[4] = *(float4*)&Bs[kk * 128 + 64 + tx * 4];
#pragma unroll
            for (int i = 0; i < 8; i++)
#pragma unroll
                for (int j = 0; j < 8; j++)
                    acc[i][j] += a[i] * bb[j];
        }
        __syncthreads();
    }

    const int c0    = by * 128;
    const int nloc0 = (bx & 7) * 128;
#pragma unroll
    for (int i = 0; i < 8; i++) {
        int c = c0 + ((i < 4) ? (ty * 4 + i) : (64 + ty * 4 + (i - 4)));
        float bias = bo[c];
        size_t base = (size_t)b * CC * NN + (size_t)c * NN + nloc0;
        float4 x0 = *(const float4*)&x[base + tx * 4];
        float4 x1 = *(const float4*)&x[base + 64 + tx * 4];
        float4 v0, v1;
        v0.x = acc[i][0] + bias + x0.x; v0.y = acc[i][1] + bias + x0.y;
        v0.z = acc[i][2] + bias + x0.z; v0.w = acc[i][3] + bias + x0.w;
        v1.x = acc[i][4] + bias + x1.x; v1.y = acc[i][5] + bias + x1.y;
        v1.z = acc[i][6] + bias + x1.z; v1.w = acc[i][7] + bias + x1.w;
        *(float4*)&out[base + tx * 4]      = v0;
        *(float4*)&out[base + 64 + tx * 4] = v1;
    }
}

// ---------------------------------------------------------------------------
extern "C" void kernel_launch(void* const* d_in, const int* in_sizes, int n_in,
                              void* d_out, int out_size)
{
    const float* x  = (const float*)d_in[0];
    const float* Wq = (const float*)d_in[1];
    const float* bq = (const float*)d_in[2];
    const float* Wo = (const float*)d_in[3];
    const float* bo = (const float*)d_in[4];
    float* out = (float*)d_out;

    // QKV projection
    k_qkv<<<dim3(12, 64), 256>>>(x, Wq, bq);

    // Flash attention (needs >48KB dynamic smem)
    const int smem = (3 * 64 * TS + 64 * 64) * (int)sizeof(float);  // 67072 B
    cudaFuncSetAttribute(k_attn, cudaFuncAttributeMaxDynamicSharedMemorySize, smem);
    k_attn<<<dim3(16, HEADS, BB), 256, smem>>>();

    // Output projection + bias + residual (writes [B,C,H,W] layout directly)
    k_proj<<<dim3(64, 4), 256>>>(Wo, bo, x, out);
}

// round 3
// speedup vs baseline: 1.0572x; 1.0572x over previous
#include <cuda_runtime.h>
#include <math.h>

// Problem constants
#define BB    8
#define CC    512
#define NN    1024        // H*W = 32*32
#define HEADS 8
#define DK    64
#define QKVC  1536        // HEADS * DK * 3
#define SCALE 0.125f      // DK^-0.5
#define TS    68          // transposed-tile stride (mult of 4 -> 16B-aligned float4)

typedef unsigned long long ull;

// Scratch (device globals; no allocation allowed)
__device__ float g_qkv[BB * NN * QKVC];   // [b*N+n][1536], per head: q(64) k(64) v(64)
__device__ float g_att[BB * NN * CC];     // [b*N+n][h*64+d]

// ---------------------------------------------------------------------------
// Packed f32x2 helpers (sm_100+): ptxas never auto-emits FFMA2.
// ---------------------------------------------------------------------------
__device__ __forceinline__ ull dup2(float v) {
    ull r;
    asm("mov.b64 %0, {%1, %1};" : "=l"(r) : "f"(v));
    return r;
}
__device__ __forceinline__ void fma2(ull& d, ull a, ull b) {
    asm("fma.rn.f32x2 %0, %1, %2, %0;" : "+l"(d) : "l"(a), "l"(b));
}
__device__ __forceinline__ void mul2(ull& d, ull a) {
    asm("mul.rn.f32x2 %0, %0, %1;" : "+l"(d) : "l"(a));
}
__device__ __forceinline__ float2 unpack2(ull v) {
    float2 f;
    asm("mov.b64 {%0, %1}, %2;" : "=f"(f.x), "=f"(f.y) : "l"(v));
    return f;
}

// ---------------------------------------------------------------------------
// Kernel 1: QKV GEMM.  C[m=8192][col=1536] = A[m][k=512] * Wq[k][col] + bq
// 128x128 tile, BK=8, 256 threads, 8x8 microtile, FFMA2 packed along cols,
// 2-stage smem double buffer (one barrier per BK step).
// ---------------------------------------------------------------------------
__global__ __launch_bounds__(256) void k_qkv(const float* __restrict__ x,
                                             const float* __restrict__ Wq,
                                             const float* __restrict__ bq)
{
    __shared__ float As[2][8 * 128];   // As[buf][k][m]
    __shared__ float Bs[2][8 * 128];   // Bs[buf][k][col]

    const int tid = threadIdx.x;
    const int tx  = tid & 15;
    const int ty  = tid >> 4;
    const int lm  = tid & 127;
    const int kb  = (tid >> 7) << 2;      // 0 or 4
    const int bx  = blockIdx.x;           // col tile: 0..11
    const int by  = blockIdx.y;           // m tile:   0..63

    const int b = by >> 3;
    const int n = ((by & 7) << 7) + lm;

    const float* pA = x  + (size_t)b * CC * NN + n;   // + k*NN
    const float* pB = Wq + (size_t)bx * 128 + lm;     // + k*QKVC

    ull acc[8][4];
#pragma unroll
    for (int i = 0; i < 8; i++)
#pragma unroll
        for (int j = 0; j < 4; j++) acc[i][j] = 0ull;

    // preload tile 0
#pragma unroll
    for (int i = 0; i < 4; i++) {
        As[0][(kb + i) * 128 + lm] = pA[(size_t)(kb + i) * NN];
        Bs[0][(kb + i) * 128 + lm] = pB[(size_t)(kb + i) * QKVC];
    }
    __syncthreads();

    int cur = 0;
    for (int k0 = 0; k0 < CC; k0 += 8) {
        float ra[4], rb[4];
        const bool more = (k0 + 8) < CC;
        if (more) {
#pragma unroll
            for (int i = 0; i < 4; i++) {
                ra[i] = pA[(size_t)(k0 + 8 + kb + i) * NN];
                rb[i] = pB[(size_t)(k0 + 8 + kb + i) * QKVC];
            }
        }
#pragma unroll
        for (int kk = 0; kk < 8; kk++) {
            float a[8];
            *(float4*)&a[0] = *(float4*)&As[cur][kk * 128 + ty * 4];
            *(float4*)&a[4] = *(float4*)&As[cur][kk * 128 + 64 + ty * 4];
            ulonglong2 b01 = *(ulonglong2*)&Bs[cur][kk * 128 + tx * 4];
            ulonglong2 b23 = *(ulonglong2*)&Bs[cur][kk * 128 + 64 + tx * 4];
            ull bp[4] = {b01.x, b01.y, b23.x, b23.y};
#pragma unroll
            for (int i = 0; i < 8; i++) {
                ull ad = dup2(a[i]);
#pragma unroll
                for (int j = 0; j < 4; j++) fma2(acc[i][j], ad, bp[j]);
            }
        }
        if (more) {
#pragma unroll
            for (int i = 0; i < 4; i++) {
                As[1 - cur][(kb + i) * 128 + lm] = ra[i];
                Bs[1 - cur][(kb + i) * 128 + lm] = rb[i];
            }
            __syncthreads();
            cur ^= 1;
        }
    }

    const int m0 = by * 128;
    const int c0 = bx * 128;
    float bias[8];
    *(float4*)&bias[0] = *(const float4*)&bq[c0 + tx * 4];
    *(float4*)&bias[4] = *(const float4*)&bq[c0 + 64 + tx * 4];

#pragma unroll
    for (int i = 0; i < 8; i++) {
        int m = m0 + ((i < 4) ? (ty * 4 + i) : (64 + ty * 4 + (i - 4)));
        float2 u0 = unpack2(acc[i][0]);
        float2 u1 = unpack2(acc[i][1]);
        float2 u2 = unpack2(acc[i][2]);
        float2 u3 = unpack2(acc[i][3]);
        float4 v0, v1;
        v0.x = u0.x + bias[0]; v0.y = u0.y + bias[1];
        v0.z = u1.x + bias[2]; v0.w = u1.y + bias[3];
        v1.x = u2.x + bias[4]; v1.y = u2.y + bias[5];
        v1.z = u3.x + bias[6]; v1.w = u3.y + bias[7];
        *(float4*)&g_qkv[(size_t)m * QKVC + c0 + tx * 4]      = v0;
        *(float4*)&g_qkv[(size_t)m * QKVC + c0 + 64 + tx * 4] = v1;
    }
}

// ---------------------------------------------------------------------------
// Kernel 2: flash attention per (b, h, qtile=64 rows).
// 256 threads as 16x16, 4x4 microtiles, FFMA2 packed.
// Smem: Qs/Ks/Ps transposed [64][TS=68], Vs natural [64][64].
// ---------------------------------------------------------------------------
__global__ __launch_bounds__(256, 2) void k_attn()
{
    extern __shared__ float sm[];
    float* Qs = sm;               // Qs[d][row]  stride TS
    float* Ks = Qs + 64 * TS;     // Ks[d][key]  stride TS
    float* Ps = Ks + 64 * TS;     // Ps[key][row] stride TS
    float* Vs = Ps + 64 * TS;     // Vs[key][d]  stride 64

    const int tid = threadIdx.x;
    const int tx  = tid & 15;
    const int ty  = tid >> 4;
    const int qt  = blockIdx.x;   // 0..15
    const int h   = blockIdx.y;   // 0..7
    const int b   = blockIdx.z;   // 0..7

    const size_t head_base = (size_t)b * NN * QKVC + (size_t)h * (3 * DK);

    // Load Q tile transposed, scaled
#pragma unroll
    for (int e = 0; e < 4; e++) {
        int idx = tid + e * 256;
        int row = idx >> 4;
        int d4  = (idx & 15) * 4;
        float4 v = *(const float4*)&g_qkv[head_base + (size_t)(qt * 64 + row) * QKVC + d4];
        Qs[(d4 + 0) * TS + row] = v.x * SCALE;
        Qs[(d4 + 1) * TS + row] = v.y * SCALE;
        Qs[(d4 + 2) * TS + row] = v.z * SCALE;
        Qs[(d4 + 3) * TS + row] = v.w * SCALE;
    }

    ull o2[4][2];
    float mi[4], li[4];
#pragma unroll
    for (int i = 0; i < 4; i++) {
        mi[i] = -1e30f; li[i] = 0.f;
        o2[i][0] = 0ull; o2[i][1] = 0ull;
    }

    for (int kt = 0; kt < 16; kt++) {
        __syncthreads();   // prev O-GEMM reads done; Qs visible (iter 0)
#pragma unroll
        for (int e = 0; e < 4; e++) {
            int idx = tid + e * 256;
            int row = idx >> 4;
            int d4  = (idx & 15) * 4;
            size_t g = head_base + (size_t)(kt * 64 + row) * QKVC;
            float4 kv = *(const float4*)&g_qkv[g + 64 + d4];
            Ks[(d4 + 0) * TS + row] = kv.x;
            Ks[(d4 + 1) * TS + row] = kv.y;
            Ks[(d4 + 2) * TS + row] = kv.z;
            Ks[(d4 + 3) * TS + row] = kv.w;
            float4 vv = *(const float4*)&g_qkv[g + 128 + d4];
            *(float4*)&Vs[row * 64 + d4] = vv;
        }
        __syncthreads();

        // S = (Q*scale) @ K^T  (4x4 per thread, packed along key cols)
        ull s2[4][2];
#pragma unroll
        for (int i = 0; i < 4; i++) { s2[i][0] = 0ull; s2[i][1] = 0ull; }

#pragma unroll
        for (int kk = 0; kk < 64; kk++) {
            float4 q = *(float4*)&Qs[kk * TS + ty * 4];
            ulonglong2 kp = *(ulonglong2*)&Ks[kk * TS + tx * 4];
            ull qd[4] = {dup2(q.x), dup2(q.y), dup2(q.z), dup2(q.w)};
#pragma unroll
            for (int i = 0; i < 4; i++) {
                fma2(s2[i][0], qd[i], kp.x);
                fma2(s2[i][1], qd[i], kp.y);
            }
        }

        // unpack S, online softmax per row (16 tx-threads share a row)
        float s[4][4];
#pragma unroll
        for (int i = 0; i < 4; i++) {
            float2 u0 = unpack2(s2[i][0]);
            float2 u1 = unpack2(s2[i][1]);
            s[i][0] = u0.x; s[i][1] = u0.y; s[i][2] = u1.x; s[i][3] = u1.y;
        }

#pragma unroll
        for (int i = 0; i < 4; i++) {
            float rm = fmaxf(fmaxf(s[i][0], s[i][1]), fmaxf(s[i][2], s[i][3]));
#pragma unroll
            for (int off = 8; off; off >>= 1)
                rm = fmaxf(rm, __shfl_xor_sync(0xffffffffu, rm, off));
            float mnew  = fmaxf(mi[i], rm);
            float alpha = __expf(mi[i] - mnew);
            mi[i] = mnew;
            float rs = 0.f;
#pragma unroll
            for (int j = 0; j < 4; j++) {
                float p = __expf(s[i][j] - mnew);
                s[i][j] = p;
                rs += p;
            }
#pragma unroll
            for (int off = 8; off; off >>= 1)
                rs += __shfl_xor_sync(0xffffffffu, rs, off);
            li[i] = li[i] * alpha + rs;
            ull ad = dup2(alpha);
            mul2(o2[i][0], ad);
            mul2(o2[i][1], ad);
        }

        // store P transposed: Ps[key][row]
#pragma unroll
        for (int i = 0; i < 4; i++)
#pragma unroll
            for (int j = 0; j < 4; j++)
                Ps[(tx * 4 + j) * TS + ty * 4 + i] = s[i][j];
        __syncthreads();

        // O += P @ V (packed along d cols)
#pragma unroll
        for (int kk = 0; kk < 64; kk++) {
            float4 p = *(float4*)&Ps[kk * TS + ty * 4];
            ulonglong2 vp = *(ulonglong2*)&Vs[kk * 64 + tx * 4];
            ull pd[4] = {dup2(p.x), dup2(p.y), dup2(p.z), dup2(p.w)};
#pragma unroll
            for (int i = 0; i < 4; i++) {
                fma2(o2[i][0], pd[i], vp.x);
                fma2(o2[i][1], pd[i], vp.y);
            }
        }
    }

    // normalize + write [bn][h*64+d]
#pragma unroll
    for (int i = 0; i < 4; i++) {
        float inv = 1.f / li[i];
        float2 u0 = unpack2(o2[i][0]);
        float2 u1 = unpack2(o2[i][1]);
        float4 v;
        v.x = u0.x * inv; v.y = u0.y * inv;
        v.z = u1.x * inv; v.w = u1.y * inv;
        int row = qt * 64 + ty * 4 + i;
        *(float4*)&g_att[((size_t)(b * NN + row)) * CC + h * DK + tx * 4] = v;
    }
}

// ---------------------------------------------------------------------------
// Kernel 3: out = att @ W_out + b_out + residual, written as [b][c][n].
// GEMM computed transposed: rows = c (512), cols = bn (8192), K = 512.
// FFMA2 packed along n cols, 2-stage double buffer.
// ---------------------------------------------------------------------------
__global__ __launch_bounds__(256) void k_proj(const float* __restrict__ Wo,
                                              const float* __restrict__ bo,
                                              const float* __restrict__ x,
                                              float* __restrict__ out)
{
    __shared__ float As[2][8 * 128];   // As[buf][e][c]
    __shared__ float Bs[2][8 * 128];   // Bs[buf][e][n]

    const int tid = threadIdx.x;
    const int tx  = tid & 15;
    const int ty  = tid >> 4;
    const int lm  = tid & 127;
    const int kb  = (tid >> 7) << 2;
    const int bx  = blockIdx.x;     // bn tile: 0..63
    const int by  = blockIdx.y;     // c tile:  0..3

    const int nn = tid >> 1;            // 0..127 (B-tile load)
    const int e4 = (tid & 1) * 4;       // 0 or 4
    const int b  = bx >> 3;
    const int bn0 = bx * 128;

    const float* pA = Wo + by * 128 + lm;                        // + e*CC
    const float* pB = g_att + (size_t)(bn0 + nn) * CC + e4;      // + k0

    ull acc[8][4];
#pragma unroll
    for (int i = 0; i < 8; i++)
#pragma unroll
        for (int j = 0; j < 4; j++) acc[i][j] = 0ull;

    // preload tile 0
#pragma unroll
    for (int i = 0; i < 4; i++)
        As[0][(kb + i) * 128 + lm] = pA[(size_t)(kb + i) * CC];
    {
        float4 bv = *(const float4*)&pB[0];
        Bs[0][(e4 + 0) * 128 + nn] = bv.x;
        Bs[0][(e4 + 1) * 128 + nn] = bv.y;
        Bs[0][(e4 + 2) * 128 + nn] = bv.z;
        Bs[0][(e4 + 3) * 128 + nn] = bv.w;
    }
    __syncthreads();

    int cur = 0;
    for (int k0 = 0; k0 < CC; k0 += 8) {
        float ra[4];
        float4 rb;
        const bool more = (k0 + 8) < CC;
        if (more) {
#pragma unroll
            for (int i = 0; i < 4; i++)
                ra[i] = pA[(size_t)(k0 + 8 + kb + i) * CC];
            rb = *(const float4*)&pB[k0 + 8];
        }
#pragma unroll
        for (int kk = 0; kk < 8; kk++) {
            float a[8];
            *(float4*)&a[0] = *(float4*)&As[cur][kk * 128 + ty * 4];
            *(float4*)&a[4] = *(float4*)&As[cur][kk * 128 + 64 + ty * 4];
            ulonglong2 b01 = *(ulonglong2*)&Bs[cur][kk * 128 + tx * 4];
            ulonglong2 b23 = *(ulonglong2*)&Bs[cur][kk * 128 + 64 + tx * 4];
            ull bp[4] = {b01.x, b01.y, b23.x, b23.y};
#pragma unroll
            for (int i = 0; i < 8; i++) {
                ull ad = dup2(a[i]);
#pragma unroll
                for (int j = 0; j < 4; j++) fma2(acc[i][j], ad, bp[j]);
            }
        }
        if (more) {
#pragma unroll
            for (int i = 0; i < 4; i++)
                As[1 - cur][(kb + i) * 128 + lm] = ra[i];
            Bs[1 - cur][(e4 + 0) * 128 + nn] = rb.x;
            Bs[1 - cur][(e4 + 1) * 128 + nn] = rb.y;
            Bs[1 - cur][(e4 + 2) * 128 + nn] = rb.z;
            Bs[1 - cur][(e4 + 3) * 128 + nn] = rb.w;
            __syncthreads();
            cur ^= 1;
        }
    }

    const int c0    = by * 128;
    const int nloc0 = (bx & 7) * 128;
#pragma unroll
    for (int i = 0; i < 8; i++) {
        int c = c0 + ((i < 4) ? (ty * 4 + i) : (64 + ty * 4 + (i - 4)));
        float bias = bo[c];
        size_t base = (size_t)b * CC * NN + (size_t)c * NN + nloc0;
        float4 x0 = *(const float4*)&x[base + tx * 4];
        float4 x1 = *(const float4*)&x[base + 64 + tx * 4];
        float2 u0 = unpack2(acc[i][0]);
        float2 u1 = unpack2(acc[i][1]);
        float2 u2 = unpack2(acc[i][2]);
        float2 u3 = unpack2(acc[i][3]);
        float4 v0, v1;
        v0.x = u0.x + bias + x0.x; v0.y = u0.y + bias + x0.y;
        v0.z = u1.x + bias + x0.z; v0.w = u1.y + bias + x0.w;
        v1.x = u2.x + bias + x1.x; v1.y = u2.y + bias + x1.y;
        v1.z = u3.x + bias + x1.z; v1.w = u3.y + bias + x1.w;
        *(float4*)&out[base + tx * 4]      = v0;
        *(float4*)&out[base + 64 + tx * 4] = v1;
    }
}

// ---------------------------------------------------------------------------
extern "C" void kernel_launch(void* const* d_in, const int* in_sizes, int n_in,
                              void* d_out, int out_size)
{
    const float* x  = (const float*)d_in[0];
    const float* Wq = (const float*)d_in[1];
    const float* bq = (const float*)d_in[2];
    const float* Wo = (const float*)d_in[3];
    const float* bo = (const float*)d_in[4];
    float* out = (float*)d_out;

    // QKV projection
    k_qkv<<<dim3(12, 64), 256>>>(x, Wq, bq);

    // Flash attention (needs >48KB dynamic smem)
    const int smem = (3 * 64 * TS + 64 * 64) * (int)sizeof(float);  // 68608 B
    cudaFuncSetAttribute(k_attn, cudaFuncAttributeMaxDynamicSharedMemorySize, smem);
    k_attn<<<dim3(16, HEADS, BB), 256, smem>>>();

    // Output projection + bias + residual (writes [B,C,H,W] layout directly)
    k_proj<<<dim3(64, 4), 256>>>(Wo, bo, x, out);
}